// round 7
// baseline (speedup 1.0000x reference)
#include <cuda_runtime.h>

#define NW 12
#define NL 3
#define DIM 4096
#define BATCH 512
#define NT 512
#define PADDED (DIM + DIM / 8)           // 4608 elements
#define DYN_SMEM (PADDED * 16)           // 73,728 B of ulonglong2 {re,im}

typedef unsigned long long ull;

__device__ __forceinline__ ull pk(float lo, float hi) {
    ull r; asm("mov.b64 %0,{%1,%2};" : "=l"(r) : "f"(lo), "f"(hi)); return r;
}
__device__ __forceinline__ void unpk(ull v, float& a, float& b) {
    asm("mov.b64 {%0,%1},%2;" : "=f"(a), "=f"(b) : "l"(v));
}
__device__ __forceinline__ ull mul2(ull a, ull b) {
    ull r; asm("mul.rn.f32x2 %0,%1,%2;" : "=l"(r) : "l"(a), "l"(b)); return r;
}
__device__ __forceinline__ ull fma2(ull a, ull b, ull c) {
    ull r; asm("fma.rn.f32x2 %0,%1,%2,%3;" : "=l"(r) : "l"(a), "l"(b), "l"(c)); return r;
}
__device__ __forceinline__ ull neg2(ull v) { return v ^ 0x8000000080000000ULL; }

// pad every 8 -> conflict-free 128-bit remap phases
__device__ __forceinline__ int pidx(int i) { return i + (i >> 3); }

// 8 packed amps (2 batch elems per lane). Local bit j <-> wire (wbase - j).
__device__ __forceinline__ void apply_group3(ull ar[8], ull ai[8],
                                             const float4 (*__restrict__ Usm)[2],
                                             int bg, int wbase)
{
#pragma unroll
    for (int j = 0; j < 3; j++) {
        float4 ua = Usm[bg + (wbase - j)][0];  // u00r,u00i,u01r,u01i
        float4 ub = Usm[bg + (wbase - j)][1];  // u10r,u10i,u11r,u11i
        ull A0r = pk(ua.x, ua.x), A0i = pk(ua.y, ua.y);
        ull A1r = pk(ua.z, ua.z), A1i = pk(ua.w, ua.w);
        ull B0r = pk(ub.x, ub.x), B0i = pk(ub.y, ub.y);
        ull B1r = pk(ub.z, ub.z), B1i = pk(ub.w, ub.w);
#pragma unroll
        for (int p = 0; p < 4; p++) {
            int k0 = ((p >> j) << (j + 1)) | (p & ((1 << j) - 1));
            int k1 = k0 | (1 << j);
            ull R0 = ar[k0], Q0 = ai[k0], R1 = ar[k1], Q1 = ai[k1];
            ull Q0n = neg2(Q0), Q1n = neg2(Q1);
            ar[k0] = fma2(A0r, R0, fma2(A0i, Q0n, fma2(A1r, R1, mul2(A1i, Q1n))));
            ai[k0] = fma2(A0r, Q0, fma2(A0i, R0,  fma2(A1r, Q1, mul2(A1i, R1))));
            ar[k1] = fma2(B0r, R0, fma2(B0i, Q0n, fma2(B1r, R1, mul2(B1i, Q1n))));
            ai[k1] = fma2(B0r, Q0, fma2(B0i, R0,  fma2(B1r, Q1, mul2(B1i, R1))));
        }
    }
}

__global__ __launch_bounds__(NT, 2)
void qsim_kernel(const float* __restrict__ state,
                 const float* __restrict__ weights,
                 const float* __restrict__ head_w,
                 const float* __restrict__ head_b,
                 float* __restrict__ out)
{
    extern __shared__ ulonglong2 buf[];    // [PADDED] {re_pack, im_pack}
    __shared__ float4 Usm[NL * NW][2];
    __shared__ float hw[NW];
    __shared__ ull warpsum[NT / 32];

    const int tid = threadIdx.x;
    const int b = blockIdx.x;  // handles batch rows 2b, 2b+1

    // ---- gate matrices U = RZ(c) RY(b) RX(a) ----
    if (tid < NL * NW) {
        float a = weights[tid * 3 + 0];
        float bb = weights[tid * 3 + 1];
        float c = weights[tid * 3 + 2];
        float sa, ca, sb, cb, sc, cc;
        sincosf(0.5f * a, &sa, &ca);
        sincosf(0.5f * bb, &sb, &cb);
        sincosf(0.5f * c, &sc, &cc);
        float m00r = cb * ca, m00i = sb * sa;
        float m01r = -sb * ca, m01i = -cb * sa;
        float m10r = sb * ca, m10i = -cb * sa;
        float m11r = cb * ca, m11i = -sb * sa;
        float4 uA, uB;
        uA.x = m00r * cc + m00i * sc;  uA.y = m00i * cc - m00r * sc;
        uA.z = m01r * cc + m01i * sc;  uA.w = m01i * cc - m01r * sc;
        uB.x = m10r * cc - m10i * sc;  uB.y = m10i * cc + m10r * sc;
        uB.z = m11r * cc - m11i * sc;  uB.w = m11i * cc + m11r * sc;
        Usm[tid][0] = uA;
        Usm[tid][1] = uB;
    }
    if (tid < NW) hw[tid] = head_w[tid];

    // ---- load two batch rows, pack into lanes (mapping A: i = (tid<<3)|k) ----
    ull ar[8], ai[8];
    const float4* s0 = (const float4*)(state + (size_t)(2 * b) * DIM);
    const float4* s1 = (const float4*)(state + (size_t)(2 * b + 1) * DIM);
#pragma unroll
    for (int q = 0; q < 2; q++) {
        float4 v0 = s0[tid * 2 + q];
        float4 v1 = s1[tid * 2 + q];
        ar[4 * q + 0] = pk(v0.x, v1.x);
        ar[4 * q + 1] = pk(v0.y, v1.y);
        ar[4 * q + 2] = pk(v0.z, v1.z);
        ar[4 * q + 3] = pk(v0.w, v1.w);
        ai[4 * q + 0] = 0ULL; ai[4 * q + 1] = 0ULL;
        ai[4 * q + 2] = 0ULL; ai[4 * q + 3] = 0ULL;
    }
    __syncthreads();  // Usm / hw ready

    for (int l = 0; l < NL; l++) {
        const int bg = l * NW;

        // group A: index bits 0-2 local -> wires 11..9
        apply_group3(ar, ai, Usm, bg, 11);

        // remap A -> B
        __syncthreads();
#pragma unroll
        for (int k = 0; k < 8; k++)
            buf[tid * 9 + k] = make_ulonglong2(ar[k], ai[k]);  // pidx((tid<<3)|k)
        __syncthreads();
#pragma unroll
        for (int k = 0; k < 8; k++) {
            int i = ((tid >> 3) << 6) | (k << 3) | (tid & 7);
            ulonglong2 v = buf[pidx(i)];
            ar[k] = v.x; ai[k] = v.y;
        }

        // group B: index bits 3-5 local -> wires 8..6
        apply_group3(ar, ai, Usm, bg, 8);

        // remap B -> C
        __syncthreads();
#pragma unroll
        for (int k = 0; k < 8; k++) {
            int i = ((tid >> 3) << 6) | (k << 3) | (tid & 7);
            buf[pidx(i)] = make_ulonglong2(ar[k], ai[k]);
        }
        __syncthreads();
#pragma unroll
        for (int k = 0; k < 8; k++) {
            int i = ((tid >> 6) << 9) | (k << 6) | (tid & 63);
            ulonglong2 v = buf[pidx(i)];
            ar[k] = v.x; ai[k] = v.y;
        }

        // group C: index bits 6-8 local -> wires 5..3
        apply_group3(ar, ai, Usm, bg, 5);

        // remap C -> D
        __syncthreads();
#pragma unroll
        for (int k = 0; k < 8; k++) {
            int i = ((tid >> 6) << 9) | (k << 6) | (tid & 63);
            buf[pidx(i)] = make_ulonglong2(ar[k], ai[k]);
        }
        __syncthreads();
#pragma unroll
        for (int k = 0; k < 8; k++) {
            int i = (k << 9) | tid;
            ulonglong2 v = buf[pidx(i)];
            ar[k] = v.x; ai[k] = v.y;
        }

        // group D: index bits 9-11 local -> wires 2..0
        apply_group3(ar, ai, Usm, bg, 2);

        // layer boundary: remap D -> A fused with CNOT-chain perm
        // psi_new[y] = psi_old[y ^ (y>>1)]
        if (l < NL - 1) {
            __syncthreads();
#pragma unroll
            for (int k = 0; k < 8; k++) {
                int i = (k << 9) | tid;
                buf[pidx(i)] = make_ulonglong2(ar[k], ai[k]);
            }
            __syncthreads();
#pragma unroll
            for (int k = 0; k < 8; k++) {
                int y = (tid << 3) | k;
                int src = y ^ (y >> 1);
                ulonglong2 v = buf[pidx(src)];
                ar[k] = v.x; ai[k] = v.y;
            }
        }
    }

    // ---- measurement (mapping D), last CNOT perm folded into weights ----
    // stored amp x = (k<<9)|tid gets weight c(y), y = suffixXOR12(x)
    int m9 = tid;
    m9 ^= m9 >> 1; m9 ^= m9 >> 2; m9 ^= m9 >> 4; m9 ^= m9 >> 8;  // suffix-XOR, 9 bits
    float c_low = 0.f;
#pragma unroll
    for (int w = 3; w < 12; w++) {
        c_low += ((m9 >> (11 - w)) & 1) ? -hw[w] : hw[w];
    }
    ull acc2 = 0ULL;
#pragma unroll
    for (int k = 0; k < 8; k++) {
        int g = k;
        g ^= g >> 1; g ^= g >> 2;  // suffix-XOR over 3 bits
        float c_high = 0.f;
#pragma unroll
        for (int w = 0; w < 3; w++) {
            c_high += ((g >> (2 - w)) & 1) ? -hw[w] : hw[w];
        }
        float c = c_high + ((g & 1) ? -c_low : c_low);  // parity(k) flips low bits
        ull pr2 = fma2(ar[k], ar[k], mul2(ai[k], ai[k]));  // |psi|^2 both lanes
        acc2 = fma2(pr2, pk(c, c), acc2);
    }
#pragma unroll
    for (int o = 16; o > 0; o >>= 1) {
        float lo, hi;
        unpk(acc2, lo, hi);
        lo += __shfl_xor_sync(0xffffffffu, lo, o);
        hi += __shfl_xor_sync(0xffffffffu, hi, o);
        acc2 = pk(lo, hi);
    }
    if ((tid & 31) == 0) warpsum[tid >> 5] = acc2;
    __syncthreads();
    if (tid == 0) {
        float slo = 0.f, shi = 0.f;
#pragma unroll
        for (int i = 0; i < NT / 32; i++) {
            float lo, hi;
            unpk(warpsum[i], lo, hi);
            slo += lo; shi += hi;
        }
        float bias = head_b[0];
        out[2 * b + 0] = slo + bias;
        out[2 * b + 1] = shi + bias;
    }
}

extern "C" void kernel_launch(void* const* d_in, const int* in_sizes, int n_in,
                              void* d_out, int out_size)
{
    const float* state   = (const float*)d_in[0];  // (512, 4096)
    const float* weights = (const float*)d_in[1];  // (3, 12, 3)
    const float* head_w  = (const float*)d_in[2];  // (1, 12)
    const float* head_b  = (const float*)d_in[3];  // (1,)
    float* out = (float*)d_out;                    // (512,)
    cudaFuncSetAttribute(qsim_kernel, cudaFuncAttributeMaxDynamicSharedMemorySize, DYN_SMEM);
    qsim_kernel<<<BATCH / 2, NT, DYN_SMEM>>>(state, weights, head_w, head_b, out);
}

// round 8
// speedup vs baseline: 1.2797x; 1.2797x over previous
#include <cuda_runtime.h>

#define NW 12
#define NL 3
#define DIM 4096
#define BATCH 512
#define NT 256
#define PADDED (DIM + DIM / 16)          // 4352 elements
#define DYN_SMEM (PADDED * 16)           // 69,632 B of ulonglong2 {re,im}

typedef unsigned long long ull;

__device__ __forceinline__ ull pk(float lo, float hi) {
    ull r; asm("mov.b64 %0,{%1,%2};" : "=l"(r) : "f"(lo), "f"(hi)); return r;
}
__device__ __forceinline__ void unpk(ull v, float& a, float& b) {
    asm("mov.b64 {%0,%1},%2;" : "=f"(a), "=f"(b) : "l"(v));
}
__device__ __forceinline__ ull mul2(ull a, ull b) {
    ull r; asm("mul.rn.f32x2 %0,%1,%2;" : "=l"(r) : "l"(a), "l"(b)); return r;
}
__device__ __forceinline__ ull fma2(ull a, ull b, ull c) {
    ull r; asm("fma.rn.f32x2 %0,%1,%2,%3;" : "=l"(r) : "l"(a), "l"(b), "l"(c)); return r;
}
__device__ __forceinline__ float2 cmulf(float2 a, float2 b) {
    return make_float2(a.x * b.x - a.y * b.y, a.x * b.y + a.y * b.x);
}

// pad every 16 -> conflict-free 128-bit remap phases
__device__ __forceinline__ int pidx(int i) { return i + (i >> 4); }

// 16 packed amps (2 batch elems per lane). Real RY gates only.
// Local bit j <-> wire (wbase - j).
__device__ __forceinline__ void apply_group(ull ar[16], ull ai[16],
                                            const float2* __restrict__ Ucs,
                                            int bg, int wbase)
{
#pragma unroll
    for (int j = 0; j < 4; j++) {
        float2 cs = Ucs[bg + (wbase - j)];
        ull C = pk(cs.x, cs.x), S = pk(cs.y, cs.y), Sn = pk(-cs.y, -cs.y);
#pragma unroll
        for (int p = 0; p < 8; p++) {
            int k0 = ((p >> j) << (j + 1)) | (p & ((1 << j) - 1));
            int k1 = k0 | (1 << j);
            ull R0 = ar[k0], Q0 = ai[k0], R1 = ar[k1], Q1 = ai[k1];
            ar[k0] = fma2(Sn, R1, mul2(C, R0));
            ai[k0] = fma2(Sn, Q1, mul2(C, Q0));
            ar[k1] = fma2(S, R0, mul2(C, R1));
            ai[k1] = fma2(S, Q0, mul2(C, Q1));
        }
    }
}

__global__ __launch_bounds__(NT, 2)
void qsim_kernel(const float* __restrict__ state,
                 const float* __restrict__ weights,
                 const float* __restrict__ head_w,
                 const float* __restrict__ head_b,
                 float* __restrict__ out)
{
    extern __shared__ ulonglong2 buf[];    // [PADDED] {re_pack, im_pack}
    __shared__ float2 Ucs[NL * NW];        // (cos th/2, sin th/2) per gate
    __shared__ float alpha1[NL * NW];      // D1 phase (|1> rel phase), gauge a0=0
    __shared__ float dgam[NL * NW];        // D2 phase delta (g1 - g0)
    __shared__ float2 TAlo[NL][64], TAhi[NL][64];   // e^{i phi1} half tables
    __shared__ float2 TGlo[NL - 1][64], TGhi[NL - 1][64];  // e^{i phi2}
    __shared__ float hw[NW];
    __shared__ ull warpsum[NT / 32];

    const int tid = threadIdx.x;
    const int b = blockIdx.x;  // handles batch rows 2b, 2b+1

    // ---- issue global loads early ----
    const float4* s0p = (const float4*)(state + (size_t)(2 * b) * DIM);
    const float4* s1p = (const float4*)(state + (size_t)(2 * b + 1) * DIM);
    float4 v0[4], v1[4];
#pragma unroll
    for (int q = 0; q < 4; q++) { v0[q] = s0p[tid * 4 + q]; v1[q] = s1p[tid * 4 + q]; }

    // ---- per-gate ZYZ decomposition: U = e^{id} D2 RY(th) D1 ----
    if (tid < NL * NW) {
        float a = weights[tid * 3 + 0];
        float bb = weights[tid * 3 + 1];
        float c = weights[tid * 3 + 2];
        float sa, ca, sb, cb, sc, cc;
        sincosf(0.5f * a, &sa, &ca);
        sincosf(0.5f * bb, &sb, &cb);
        sincosf(0.5f * c, &sc, &cc);
        float m00r = cb * ca, m00i = sb * sa;
        float m01r = -sb * ca, m01i = -cb * sa;
        float m10r = sb * ca, m10i = -cb * sa;
        float m11r = cb * ca, m11i = -sb * sa;
        // u00,u01 (row0 with e^{-ic/2}); u10,u11 (row1 with e^{+ic/2})
        float u00r = m00r * cc + m00i * sc, u00i = m00i * cc - m00r * sc;
        float u01r = m01r * cc + m01i * sc, u01i = m01i * cc - m01r * sc;
        float u10r = m10r * cc - m10i * sc, u10i = m10i * cc + m10r * sc;
        float cth = sqrtf(u00r * u00r + u00i * u00i);
        float sth = sqrtf(u10r * u10r + u10i * u10i);
        float g0 = atan2f(u00i, u00r);
        float g1 = atan2f(u10i, u10r);
        float a1 = atan2f(-u01i, -u01r) - g0;
        Ucs[tid] = make_float2(cth, sth);
        alpha1[tid] = a1;
        dgam[tid] = g1 - g0;
    }
    if (tid < NW) hw[tid] = head_w[tid];
    __syncthreads();

    // ---- build phase half-tables (threads 0..63) ----
    // phi1^l(x) = sum_j x_j * alpha1[l][11-j] ; lo bits j=0..5 -> wires 11..6
    if (tid < 64) {
        int m = tid;
#pragma unroll
        for (int l = 0; l < NL; l++) {
            float plo = 0.f, phi = 0.f, qlo = 0.f, qhi = 0.f;
#pragma unroll
            for (int j = 0; j < 6; j++) {
                if ((m >> j) & 1) {
                    plo += alpha1[l * NW + 11 - j];
                    phi += alpha1[l * NW + 5 - j];
                    qlo += dgam[l * NW + 11 - j];
                    qhi += dgam[l * NW + 5 - j];
                }
            }
            float cv, sv;
            sincosf(plo, &sv, &cv); TAlo[l][m] = make_float2(cv, sv);
            sincosf(phi, &sv, &cv); TAhi[l][m] = make_float2(cv, sv);
            if (l < NL - 1) {
                sincosf(qlo, &sv, &cv); TGlo[l][m] = make_float2(cv, sv);
                sincosf(qhi, &sv, &cv); TGhi[l][m] = make_float2(cv, sv);
            }
        }
    }
    __syncthreads();

    // ---- init: psi = e^{i phi1^0(x)} * s(x), mapping A: x = (tid<<4)|k ----
    ull ar[16], ai[16];
    {
        float2 hiC = TAhi[0][tid >> 2];  // x>>6 = tid>>2, constant per thread
#pragma unroll
        for (int q = 0; q < 4; q++) {
            float sr0[4] = {v0[q].x, v0[q].y, v0[q].z, v0[q].w};
            float sr1[4] = {v1[q].x, v1[q].y, v1[q].z, v1[q].w};
#pragma unroll
            for (int e = 0; e < 4; e++) {
                int k = 4 * q + e;
                int xlo = ((tid & 3) << 4) | k;
                float2 ph = cmulf(TAlo[0][xlo], hiC);
                ull sp = pk(sr0[e], sr1[e]);
                ar[k] = mul2(sp, pk(ph.x, ph.x));
                ai[k] = mul2(sp, pk(ph.y, ph.y));
            }
        }
    }

    for (int l = 0; l < NL; l++) {
        const int bg = l * NW;

        // group A: index bits 0-3 local -> wires 11..8
        apply_group(ar, ai, Ucs, bg, 11);

        // remap A -> B (intra-warp exchange: 16-thread groups)
        __syncthreads();  // also guards buf reuse after previous perm-read
#pragma unroll
        for (int k = 0; k < 16; k++)
            buf[tid * 17 + k] = make_ulonglong2(ar[k], ai[k]);  // pidx((tid<<4)|k)
        __syncwarp();
#pragma unroll
        for (int k = 0; k < 16; k++) {
            int i = ((tid >> 4) << 8) | (k << 4) | (tid & 15);
            ulonglong2 v = buf[pidx(i)];
            ar[k] = v.x; ai[k] = v.y;
        }

        // group B: index bits 4-7 local -> wires 7..4
        apply_group(ar, ai, Ucs, bg, 7);

        // remap B -> C (cross-warp)
        __syncthreads();
#pragma unroll
        for (int k = 0; k < 16; k++) {
            int i = ((tid >> 4) << 8) | (k << 4) | (tid & 15);
            buf[pidx(i)] = make_ulonglong2(ar[k], ai[k]);
        }
        __syncthreads();
#pragma unroll
        for (int k = 0; k < 16; k++) {
            int i = (k << 8) | tid;
            ulonglong2 v = buf[pidx(i)];
            ar[k] = v.x; ai[k] = v.y;
        }

        // group C: index bits 8-11 local -> wires 3..0
        apply_group(ar, ai, Ucs, bg, 3);

        // layer boundary: remap C -> A fused with CNOT perm AND the merged
        // diagonal D1^{l+1} . P . D2^l :
        // psi'[y] = e^{i[phi1^{l+1}(y) + phi2^l(src)]} psi[src], src = y^(y>>1)
        if (l < NL - 1) {
            __syncthreads();
#pragma unroll
            for (int k = 0; k < 16; k++) {
                int i = (k << 8) | tid;
                buf[pidx(i)] = make_ulonglong2(ar[k], ai[k]);
            }
            __syncthreads();
            // per-thread constant hi parts: y>>6 = tid>>2 ; src>>6 = (y>>6)^(y>>7)
            float2 hiC = cmulf(TGhi[l][(tid >> 2) ^ (tid >> 3)], TAhi[l + 1][tid >> 2]);
#pragma unroll
            for (int k = 0; k < 16; k++) {
                int y = (tid << 4) | k;
                int src = y ^ (y >> 1);
                ulonglong2 v = buf[pidx(src)];
                float2 loC = cmulf(TGlo[l][src & 63], TAlo[l + 1][((tid & 3) << 4) | k]);
                float2 ph = cmulf(loC, hiC);
                ull C = pk(ph.x, ph.x), S = pk(ph.y, ph.y), Sn = pk(-ph.y, -ph.y);
                ar[k] = fma2(Sn, v.y, mul2(C, v.x));
                ai[k] = fma2(S, v.x, mul2(C, v.y));
            }
        }
    }

    // ---- measurement (mapping C): final D2 dropped (|amp|^2 invariant),
    // last CNOT perm folded into weights: x = (k<<8)|tid, weight c(suffixXOR(x))
    int m8 = tid;
    m8 ^= m8 >> 1; m8 ^= m8 >> 2; m8 ^= m8 >> 4;  // suffix-XOR over 8 bits
    float c_low = 0.f;
#pragma unroll
    for (int w = 4; w < 12; w++) {
        c_low += ((m8 >> (11 - w)) & 1) ? -hw[w] : hw[w];
    }
    ull acc2 = 0ULL;
#pragma unroll
    for (int k = 0; k < 16; k++) {
        int g4 = k;
        g4 ^= g4 >> 1; g4 ^= g4 >> 2;  // suffix-XOR over 4 bits
        float c_high = 0.f;
#pragma unroll
        for (int w = 0; w < 4; w++) {
            c_high += ((g4 >> (3 - w)) & 1) ? -hw[w] : hw[w];
        }
        float c = c_high + ((g4 & 1) ? -c_low : c_low);
        ull pr2 = fma2(ar[k], ar[k], mul2(ai[k], ai[k]));  // |psi|^2 both lanes
        acc2 = fma2(pr2, pk(c, c), acc2);
    }
#pragma unroll
    for (int o = 16; o > 0; o >>= 1) {
        float lo, hi;
        unpk(acc2, lo, hi);
        lo += __shfl_xor_sync(0xffffffffu, lo, o);
        hi += __shfl_xor_sync(0xffffffffu, hi, o);
        acc2 = pk(lo, hi);
    }
    if ((tid & 31) == 0) warpsum[tid >> 5] = acc2;
    __syncthreads();
    if (tid == 0) {
        float slo = 0.f, shi = 0.f;
#pragma unroll
        for (int i = 0; i < NT / 32; i++) {
            float lo, hi;
            unpk(warpsum[i], lo, hi);
            slo += lo; shi += hi;
        }
        float bias = head_b[0];
        out[2 * b + 0] = slo + bias;
        out[2 * b + 1] = shi + bias;
    }
}

extern "C" void kernel_launch(void* const* d_in, const int* in_sizes, int n_in,
                              void* d_out, int out_size)
{
    const float* state   = (const float*)d_in[0];  // (512, 4096)
    const float* weights = (const float*)d_in[1];  // (3, 12, 3)
    const float* head_w  = (const float*)d_in[2];  // (1, 12)
    const float* head_b  = (const float*)d_in[3];  // (1,)
    float* out = (float*)d_out;                    // (512,)
    cudaFuncSetAttribute(qsim_kernel, cudaFuncAttributeMaxDynamicSharedMemorySize, DYN_SMEM);
    qsim_kernel<<<BATCH / 2, NT, DYN_SMEM>>>(state, weights, head_w, head_b, out);
}